// round 17
// baseline (speedup 1.0000x reference)
#include <cuda_runtime.h>
#include <cuda_bf16.h>
#include <math.h>
#include <stdint.h>

#define Bn   32
#define Tn   24
#define Cn   512
#define Nn   (Bn*Cn)
#define INF  14
#define HIDn 36
#define FFNn 144
#define HDn  18
#define EG   8192
#define SEQ  2
#define Rn   (SEQ*Tn)         // 48 rows per CTA
#define NT   128

// ---------------- scratch (device globals) -----------------------------------
__device__ float d_xn [Nn*Tn*INF];
__device__ float d_xn2[Nn*Tn*INF];
__device__ int   d_deg[Cn];
__device__ int   d_colcnt[Cn];
__device__ int   d_off[Cn+1];
__device__ float d_dinv[Cn];
__device__ int   d_brow[EG];
__device__ float d_bw[EG];
__device__ float d_pe[HIDn*Tn];

// bf16-split weights, [n][k] bf16x2 pairs (uint32), hi/lo planes.
#define WB_TOT   20992
#define OFF_QKVO 640
#define OFF_F1   8320
#define OFF_F2   15232
__device__ uint32_t d_wbh[WB_TOT];
__device__ uint32_t d_wbl[WB_TOT];

// ---------------- K1 ----------------------------------------------------------
__global__ void k_count(const int* __restrict__ ei) {
    int c = blockIdx.x, lane = threadIdx.x;
    int cr = 0, cc = 0;
    for (int e = lane; e < EG; e += 32) {
        cr += (ei[e]      == c);
        cc += (ei[EG + e] == c);
    }
    #pragma unroll
    for (int o = 16; o; o >>= 1) {
        cr += __shfl_down_sync(0xffffffffu, cr, o);
        cc += __shfl_down_sync(0xffffffffu, cc, o);
    }
    if (lane == 0) { d_deg[c] = cr; d_colcnt[c] = cc; }
}

// ---------------- K2 ----------------------------------------------------------
__global__ void k_scan() {
    __shared__ int s[Cn];
    int t = threadIdx.x;
    s[t] = d_colcnt[t];
    __syncthreads();
    for (int o = 1; o < Cn; o <<= 1) {
        int v = (t >= o) ? s[t - o] : 0;
        __syncthreads();
        s[t] += v;
        __syncthreads();
    }
    d_off[t + 1] = s[t];
    if (t == 0) d_off[0] = 0;
    int dg = d_deg[t];
    d_dinv[t] = (dg > 0) ? (1.0f / sqrtf((float)dg)) : 0.0f;
    for (int i = t; i < HIDn * Tn; i += Cn) {
        int o = i / Tn, tt = i % Tn;
        float div = expf(-9.210340371976184f * (float)(o & ~1) / (float)HIDn);
        float ang = (float)tt * div;
        d_pe[i] = (o & 1) ? cosf(ang) : sinf(ang);
    }
}

// ---------------- K3 ----------------------------------------------------------
__global__ void k_fill(const int* __restrict__ ei) {
    int c = blockIdx.x, lane = threadIdx.x;
    int base = d_off[c];
    float dc = d_dinv[c];
    for (int e0 = 0; e0 < EG; e0 += 32) {
        int e = e0 + lane;
        int col = ei[EG + e];
        bool m = (col == c);
        unsigned mask = __ballot_sync(0xffffffffu, m);
        if (m) {
            int pos = base + __popc(mask & ((1u << lane) - 1u));
            int r = ei[e];
            d_brow[pos] = r;
            d_bw[pos]   = -(d_dinv[r] * dc);
        }
        base += __popc(mask);
    }
}

// ---------------- K4 ----------------------------------------------------------
__global__ void k_pack(const float* __restrict__ pm, const float* __restrict__ ft) {
    int idx = blockIdx.x * blockDim.x + threadIdx.x;
    if (idx >= Nn * Tn * INF) return;
    int f  = idx % INF;
    int rt = idx / INF;
    int t  = rt % Tn;
    int n  = rt / Tn;
    int b  = n >> 9, c = n & (Cn - 1);
    float v1, v2;
    if (f == 0) {
        v1 = pm[(b * Tn + t) * Cn + c];
        v2 = v1;
    } else {
        v1 = ft[((b * 2 * Tn + t)      * Cn + c) * 13 + (f - 1)];
        v2 = ft[((b * 2 * Tn + Tn + t) * Cn + c) * 13 + (f - 1)];
    }
    d_xn [idx] = v1;
    d_xn2[idx] = v2;
}

// ---------------- K5: weight bf16 hi/lo split ---------------------------------
__global__ void k_wprep(const float* __restrict__ tinW,
                        const float* __restrict__ Wq, const float* __restrict__ Wk,
                        const float* __restrict__ Wv, const float* __restrict__ Wo,
                        const float* __restrict__ fW1, const float* __restrict__ fW2) {
    int u = blockIdx.x * blockDim.x + threadIdx.x;
    if (u >= WB_TOT) return;
    float v0 = 0.0f, v1 = 0.0f;
    if (u < OFF_QKVO) {
        int n = u / 16, p = u % 16, k = 2 * p;
        if (n < 36) {
            if (k < 28)     v0 = tinW[k * 36 + n];
            if (k + 1 < 28) v1 = tinW[(k + 1) * 36 + n];
        }
    } else if (u < OFF_F1) {
        int q = u - OFF_QKVO;
        int mat = q / 960, r = q % 960;
        int l = mat >> 2, w = mat & 3;
        int n = r / 24, p = r % 24, k = 2 * p;
        const float* W = (w == 0 ? Wq : w == 1 ? Wk : w == 2 ? Wv : Wo) + l * 1296;
        if (n < 36) {
            if (k < 36)     v0 = W[k * 36 + n];
            if (k + 1 < 36) v1 = W[(k + 1) * 36 + n];
        }
    } else if (u < OFF_F2) {
        int q = u - OFF_F1;
        int l = q / 3456, r = q % 3456;
        int n = r / 24, p = r % 24, k = 2 * p;
        const float* W = fW1 + l * 5184;
        if (k < 36)     v0 = W[k * 144 + n];
        if (k + 1 < 36) v1 = W[(k + 1) * 144 + n];
    } else {
        int q = u - OFF_F2;
        int l = q / 2880, r = q % 2880;
        int n = r / 72, p = r % 72, k = 2 * p;
        const float* W = fW2 + l * 5184;
        if (n < 36) {
            v0 = W[k * 36 + n];
            v1 = W[(k + 1) * 36 + n];
        }
    }
    __nv_bfloat16 h0 = __float2bfloat16_rn(v0);
    __nv_bfloat16 h1 = __float2bfloat16_rn(v1);
    __nv_bfloat16 l0 = __float2bfloat16_rn(v0 - __bfloat162float(h0));
    __nv_bfloat16 l1 = __float2bfloat16_rn(v1 - __bfloat162float(h1));
    d_wbh[u] = (uint32_t)__bfloat16_as_ushort(h0) | ((uint32_t)__bfloat16_as_ushort(h1) << 16);
    d_wbl[u] = (uint32_t)__bfloat16_as_ushort(l0) | ((uint32_t)__bfloat16_as_ushort(l1) << 16);
}

// ---------------- bf16 helpers -------------------------------------------------
__device__ __forceinline__ void bfpair(float v0, float v1, uint32_t& hi, uint32_t& lo) {
    __nv_bfloat16 h0 = __float2bfloat16_rn(v0);
    __nv_bfloat16 h1 = __float2bfloat16_rn(v1);
    __nv_bfloat16 l0 = __float2bfloat16_rn(v0 - __bfloat162float(h0));
    __nv_bfloat16 l1 = __float2bfloat16_rn(v1 - __bfloat162float(h1));
    hi = (uint32_t)__bfloat16_as_ushort(h0) | ((uint32_t)__bfloat16_as_ushort(h1) << 16);
    lo = (uint32_t)__bfloat16_as_ushort(l0) | ((uint32_t)__bfloat16_as_ushort(l1) << 16);
}

template<int KP>
__device__ __forceinline__ int swzm(int m) {
    if (KP == 32) return ((((m >> 1) & 1) << 4) | (((m >> 2) & 1) << 5));
    return ((m >> 2) & 1) << 4;     // pitch 96B / 288B
}

// fp32 col-major [KD][48] -> staged row-major bf16 [48][KP] hi+lo (tin only)
template<int KP, int KD>
__device__ __forceinline__ void stageA(const float* __restrict__ IN, float* Sb, int tid) {
    uint32_t* H = reinterpret_cast<uint32_t*>(Sb);
    constexpr int PLANE = 48 * KP / 2;
    for (int u = tid; u < PLANE; u += NT) {
        int m = u % 48, p = u / 48;
        int k = 2 * p;
        float v0 = (k     < KD) ? IN[k * 48 + m]       : 0.0f;
        float v1 = (k + 1 < KD) ? IN[(k + 1) * 48 + m] : 0.0f;
        uint32_t hi, lo;
        bfpair(v0, v1, hi, lo);
        int idx = ((m * (KP * 2) + p * 4) ^ swzm<KP>(m)) >> 2;
        H[idx] = hi; H[PLANE + idx] = lo;
    }
}

__device__ __forceinline__ void ldm4(uint32_t& r0, uint32_t& r1, uint32_t& r2, uint32_t& r3,
                                     uint32_t addr) {
    asm volatile("ldmatrix.sync.aligned.m8n8.x4.shared.b16 {%0,%1,%2,%3}, [%4];"
                 : "=r"(r0), "=r"(r1), "=r"(r2), "=r"(r3) : "r"(addr));
}

__device__ __forceinline__ void mma_bf16(float& c0, float& c1, float& c2, float& c3,
                                         uint32_t a0, uint32_t a1, uint32_t a2, uint32_t a3,
                                         uint32_t b0, uint32_t b1) {
    asm volatile("mma.sync.aligned.m16n8k16.row.col.f32.bf16.bf16.f32 "
                 "{%0,%1,%2,%3}, {%4,%5,%6,%7}, {%8,%9}, {%0,%1,%2,%3};"
                 : "+f"(c0), "+f"(c1), "+f"(c2), "+f"(c3)
                 : "r"(a0), "r"(a1), "r"(a2), "r"(a3), "r"(b0), "r"(b1));
}

// BALANCED single matmul NOUT=36: 15 (mt,nt) tiles over 4 warps (4/4/4/3).
template<int KP, bool RELU>
__device__ void tmmC_bal(const float* Sb,
                         const uint32_t* __restrict__ wh, const uint32_t* __restrict__ wl,
                         const float* __restrict__ bias, float* __restrict__ OUT,
                         int warp, int lane) {
    constexpr int NKT = KP / 16;
    uint32_t sbase = (uint32_t)__cvta_generic_to_shared(Sb);
    int part = lane >> 3, rr = lane & 7;
    int g = lane >> 2, q2v = (lane & 3) * 2;
    #pragma unroll
    for (int i = 0; i < 4; i++) {
        int tile = warp + 4 * i;
        if (tile < 15) {
            int mt = tile / 5, nt = tile % 5;
            float C[4] = {0.f, 0.f, 0.f, 0.f};
            #pragma unroll
            for (int kt = 0; kt < NKT; kt++) {
                int m = mt * 16 + rr + (part & 1) * 8;
                int colb = (kt * 16 + ((part >> 1) << 3)) * 2;
                uint32_t off = (uint32_t)((m * (KP * 2) + colb) ^ swzm<KP>(m));
                uint32_t ah0, ah1, ah2, ah3, al0, al1, al2, al3;
                ldm4(ah0, ah1, ah2, ah3, sbase + off);
                ldm4(al0, al1, al2, al3, sbase + 48 * KP * 2 + off);
                int pi = (nt * 8 + g) * (KP / 2) + kt * 8 + (lane & 3);
                uint32_t bh0 = __ldg(wh + pi), bh1 = __ldg(wh + pi + 4);
                uint32_t bl0 = __ldg(wl + pi), bl1 = __ldg(wl + pi + 4);
                mma_bf16(C[0], C[1], C[2], C[3], ah0, ah1, ah2, ah3, bh0, bh1);
                mma_bf16(C[0], C[1], C[2], C[3], ah0, ah1, ah2, ah3, bl0, bl1);
                mma_bf16(C[0], C[1], C[2], C[3], al0, al1, al2, al3, bh0, bh1);
            }
            int m = mt * 16 + g;
            int nA = nt * 8 + q2v, nB = nA + 1;
            if (nA < 36) {
                float bv = __ldg(bias + nA);
                float a0 = C[0] + bv, a2 = C[2] + bv;
                if (RELU) { a0 = fmaxf(a0, 0.f); a2 = fmaxf(a2, 0.f); }
                OUT[nA * 48 + m] = a0; OUT[nA * 48 + m + 8] = a2;
            }
            if (nB < 36) {
                float bv = __ldg(bias + nB);
                float a1 = C[1] + bv, a3 = C[3] + bv;
                if (RELU) { a1 = fmaxf(a1, 0.f); a3 = fmaxf(a3, 0.f); }
                OUT[nB * 48 + m] = a1; OUT[nB * 48 + m + 8] = a3;
            }
        }
    }
}

// BALANCED fused q,k,v: 15 (mat,nt) cols over 4 warps; mt outer (A reused).
__device__ void tmmC3_bal(const float* Sb,
                          const uint32_t* wh0, const uint32_t* wl0, const float* b0, float* O0,
                          const uint32_t* wh1, const uint32_t* wl1, const float* b1, float* O1,
                          const uint32_t* wh2, const uint32_t* wl2, const float* b2, float* O2,
                          int warp, int lane) {
    const uint32_t* WH[3] = {wh0, wh1, wh2};
    const uint32_t* WL[3] = {wl0, wl1, wl2};
    const float*    BB[3] = {b0, b1, b2};
    float*          OO[3] = {O0, O1, O2};
    uint32_t sbase = (uint32_t)__cvta_generic_to_shared(Sb);
    int part = lane >> 3, rr = lane & 7;
    int g = lane >> 2, q2v = (lane & 3) * 2;
    #pragma unroll
    for (int mt = 0; mt < 3; mt++) {
        float C[4][4];
        #pragma unroll
        for (int i = 0; i < 4; i++) { C[i][0]=0.f; C[i][1]=0.f; C[i][2]=0.f; C[i][3]=0.f; }
        #pragma unroll
        for (int kt = 0; kt < 3; kt++) {
            int m = mt * 16 + rr + (part & 1) * 8;
            int colb = (kt * 16 + ((part >> 1) << 3)) * 2;
            uint32_t off = (uint32_t)((m * 96 + colb) ^ swzm<48>(m));
            uint32_t ah0, ah1, ah2, ah3, al0, al1, al2, al3;
            ldm4(ah0, ah1, ah2, ah3, sbase + off);
            ldm4(al0, al1, al2, al3, sbase + 4608 + off);
            #pragma unroll
            for (int i = 0; i < 4; i++) {
                int col = warp + 4 * i;
                if (col < 15) {
                    int mat = col / 5, nt = col % 5;
                    int pi = (nt * 8 + g) * 24 + kt * 8 + (lane & 3);
                    uint32_t bh0 = __ldg(WH[mat] + pi), bh1 = __ldg(WH[mat] + pi + 4);
                    uint32_t bl0 = __ldg(WL[mat] + pi), bl1 = __ldg(WL[mat] + pi + 4);
                    mma_bf16(C[i][0], C[i][1], C[i][2], C[i][3], ah0, ah1, ah2, ah3, bh0, bh1);
                    mma_bf16(C[i][0], C[i][1], C[i][2], C[i][3], ah0, ah1, ah2, ah3, bl0, bl1);
                    mma_bf16(C[i][0], C[i][1], C[i][2], C[i][3], al0, al1, al2, al3, bh0, bh1);
                }
            }
        }
        #pragma unroll
        for (int i = 0; i < 4; i++) {
            int col = warp + 4 * i;
            if (col < 15) {
                int mat = col / 5, nt = col % 5;
                int m = mt * 16 + g;
                int nA = nt * 8 + q2v, nB = nA + 1;
                if (nA < 36) {
                    float bv = __ldg(BB[mat] + nA);
                    OO[mat][nA * 48 + m] = C[i][0] + bv;
                    OO[mat][nA * 48 + m + 8] = C[i][2] + bv;
                }
                if (nB < 36) {
                    float bv = __ldg(BB[mat] + nB);
                    OO[mat][nB * 48 + m] = C[i][1] + bv;
                    OO[mat][nB * 48 + m + 8] = C[i][3] + bv;
                }
            }
        }
    }
}

// tin (KP=32, NOUT=36): epilogue adds bias+PE, writes h fp32 AND staged bf16 S.
__device__ void tmmC_tin(const float* Sb,
                         const uint32_t* __restrict__ wh, const uint32_t* __restrict__ wl,
                         const float* __restrict__ bias,
                         float* __restrict__ hout, float* __restrict__ Sst,
                         int warp, int lane) {
    constexpr int NTN = 5, MYN = 2;
    uint32_t sbase = (uint32_t)__cvta_generic_to_shared(Sb);
    uint32_t* SU = reinterpret_cast<uint32_t*>(Sst);
    int part = lane >> 3, rr = lane & 7;
    int g = lane >> 2, q2v = (lane & 3) * 2;
    uint32_t wr[MYN][2][4];
    #pragma unroll
    for (int i = 0; i < MYN; i++) {
        int nt = warp + 4 * i;
        #pragma unroll
        for (int kt = 0; kt < 2; kt++) {
            if (nt < NTN) {
                int pi = (nt * 8 + g) * 16 + kt * 8 + (lane & 3);
                wr[i][kt][0] = __ldg(wh + pi); wr[i][kt][1] = __ldg(wh + pi + 4);
                wr[i][kt][2] = __ldg(wl + pi); wr[i][kt][3] = __ldg(wl + pi + 4);
            } else {
                wr[i][kt][0] = wr[i][kt][1] = wr[i][kt][2] = wr[i][kt][3] = 0u;
            }
        }
    }
    #pragma unroll
    for (int mt = 0; mt < 3; mt++) {
        float C[MYN][4];
        #pragma unroll
        for (int i = 0; i < MYN; i++) { C[i][0]=0.f; C[i][1]=0.f; C[i][2]=0.f; C[i][3]=0.f; }
        #pragma unroll
        for (int kt = 0; kt < 2; kt++) {
            int m = mt * 16 + rr + (part & 1) * 8;
            int colb = (kt * 16 + ((part >> 1) << 3)) * 2;
            uint32_t off = (uint32_t)((m * 64 + colb) ^ swzm<32>(m));
            uint32_t ah0, ah1, ah2, ah3, al0, al1, al2, al3;
            ldm4(ah0, ah1, ah2, ah3, sbase + off);
            ldm4(al0, al1, al2, al3, sbase + 3072 + off);
            #pragma unroll
            for (int i = 0; i < MYN; i++) {
                int nt = warp + 4 * i;
                if (nt < NTN) {
                    mma_bf16(C[i][0], C[i][1], C[i][2], C[i][3], ah0, ah1, ah2, ah3, wr[i][kt][0], wr[i][kt][1]);
                    mma_bf16(C[i][0], C[i][1], C[i][2], C[i][3], ah0, ah1, ah2, ah3, wr[i][kt][2], wr[i][kt][3]);
                    mma_bf16(C[i][0], C[i][1], C[i][2], C[i][3], al0, al1, al2, al3, wr[i][kt][0], wr[i][kt][1]);
                }
            }
        }
        #pragma unroll
        for (int i = 0; i < MYN; i++) {
            int nt = warp + 4 * i;
            if (nt < NTN) {
                int m = mt * 16 + g;
                int nA = nt * 8 + q2v, nB = nA + 1;
                if (nA < 36) {
                    int t0 = m % Tn, t1 = (m + 8) % Tn;
                    float bA = __ldg(bias + nA), bB = __ldg(bias + nB);
                    float v0 = C[i][0] + bA + __ldg(d_pe + nA * Tn + t0);
                    float v1 = C[i][1] + bB + __ldg(d_pe + nB * Tn + t0);
                    float v2 = C[i][2] + bA + __ldg(d_pe + nA * Tn + t1);
                    float v3 = C[i][3] + bB + __ldg(d_pe + nB * Tn + t1);
                    hout[nA * 48 + m] = v0;     hout[nB * 48 + m] = v1;
                    hout[nA * 48 + m + 8] = v2; hout[nB * 48 + m + 8] = v3;
                    uint32_t hi, lo;
                    int p = nA >> 1;
                    bfpair(v0, v1, hi, lo);
                    int by0 = (m * 96 + p * 4) ^ swzm<48>(m);
                    SU[by0 >> 2] = hi; SU[1152 + (by0 >> 2)] = lo;
                    bfpair(v2, v3, hi, lo);
                    int by1 = ((m + 8) * 96 + p * 4) ^ swzm<48>(m + 8);
                    SU[by1 >> 2] = hi; SU[1152 + (by1 >> 2)] = lo;
                }
            }
        }
    }
}

// ffn1: staged-A (KP=48) -> OUT staged bf16 [48][144] hi/lo in U (relu)
__device__ void tmmB(const float* Sb,
                     const uint32_t* __restrict__ wh, const uint32_t* __restrict__ wl,
                     const float* __restrict__ bias, float* __restrict__ OUTf,
                     int warp, int lane) {
    constexpr int NTN = 18;
    constexpr int MYN = 5;
    uint32_t sbase = (uint32_t)__cvta_generic_to_shared(Sb);
    uint32_t* OU = reinterpret_cast<uint32_t*>(OUTf);
    int part = lane >> 3, rr = lane & 7;
    int g = lane >> 2, q2v = (lane & 3) * 2;
    #pragma unroll
    for (int mt = 0; mt < 3; mt++) {
        float C[MYN][4];
        #pragma unroll
        for (int i = 0; i < MYN; i++) { C[i][0]=0.f; C[i][1]=0.f; C[i][2]=0.f; C[i][3]=0.f; }
        #pragma unroll
        for (int kt = 0; kt < 3; kt++) {
            int m = mt * 16 + rr + (part & 1) * 8;
            int colb = (kt * 16 + ((part >> 1) << 3)) * 2;
            uint32_t off = (uint32_t)((m * 96 + colb) ^ swzm<48>(m));
            uint32_t ah0, ah1, ah2, ah3, al0, al1, al2, al3;
            ldm4(ah0, ah1, ah2, ah3, sbase + off);
            ldm4(al0, al1, al2, al3, sbase + 4608 + off);
            #pragma unroll
            for (int i = 0; i < MYN; i++) {
                int nt = warp + 4 * i;
                if (nt < NTN) {
                    int pi = (nt * 8 + g) * 24 + kt * 8 + (lane & 3);
                    uint32_t bh0 = __ldg(wh + pi), bh1 = __ldg(wh + pi + 4);
                    uint32_t bl0 = __ldg(wl + pi), bl1 = __ldg(wl + pi + 4);
                    mma_bf16(C[i][0], C[i][1], C[i][2], C[i][3], ah0, ah1, ah2, ah3, bh0, bh1);
                    mma_bf16(C[i][0], C[i][1], C[i][2], C[i][3], ah0, ah1, ah2, ah3, bl0, bl1);
                    mma_bf16(C[i][0], C[i][1], C[i][2], C[i][3], al0, al1, al2, al3, bh0, bh1);
                }
            }
        }
        #pragma unroll
        for (int i = 0; i < MYN; i++) {
            int nt = warp + 4 * i;
            if (nt < NTN) {
                int m = mt * 16 + g;
                int nA = nt * 8 + q2v;
                float bv0 = __ldg(bias + nA), bv1 = __ldg(bias + nA + 1);
                float a0 = fmaxf(C[i][0] + bv0, 0.f), a1 = fmaxf(C[i][1] + bv1, 0.f);
                float a2 = fmaxf(C[i][2] + bv0, 0.f), a3 = fmaxf(C[i][3] + bv1, 0.f);
                int pidx = nt * 4 + (lane & 3);
                uint32_t hi, lo;
                bfpair(a0, a1, hi, lo);
                int b0 = (m * 288 + pidx * 4) ^ swzm<144>(m);
                OU[b0 >> 2] = hi; OU[3456 + (b0 >> 2)] = lo;
                bfpair(a2, a3, hi, lo);
                int b1 = ((m + 8) * 288 + pidx * 4) ^ swzm<144>(m + 8);
                OU[b1 >> 2] = hi; OU[3456 + (b1 >> 2)] = lo;
            }
        }
    }
}

// ---------------- scalar helpers ----------------------------------------------
__device__ __forceinline__ uint64_t pack2(float v) {
    uint64_t r;
    asm("mov.b64 %0, {%1, %1};" : "=l"(r) : "f"(v));
    return r;
}
__device__ __forceinline__ void fma2(uint64_t& acc, uint64_t a, uint64_t b) {
    asm("fma.rn.f32x2 %0, %1, %2, %0;" : "+l"(acc) : "l"(a), "l"(b));
}
__device__ __forceinline__ float2 unpack2(uint64_t v) {
    float lo, hi;
    asm("mov.b64 {%0, %1}, %2;" : "=f"(lo), "=f"(hi) : "l"(v));
    return make_float2(lo, hi);
}

// LN + staged emit. IB=true inserts alias-safe internal barrier (needed only
// when res aliases Sst). Uniform control flow in both variants.
template<bool IB>
__device__ __forceinline__ void layernorm2s(float* __restrict__ h,
                                            const float* __restrict__ res,
                                            const float* __restrict__ g,
                                            const float* __restrict__ bb,
                                            float* __restrict__ Sst, int tid) {
    uint32_t* SU = reinterpret_cast<uint32_t*>(Sst);
    int r = tid >> 1, half = tid & 1;
    float vloc[18];
    float m = 0.0f, rs = 0.0f;
    if (tid < 96) {
        float q2s = 0.0f;
        #pragma unroll
        for (int kk = 0; kk < 18; kk++) {
            int k = half * 18 + kk;
            float v = h[k * Rn + r] + res[k * Rn + r];
            vloc[kk] = v;
            m += v; q2s += v * v;
        }
        m   += __shfl_xor_sync(0xffffffffu, m, 1);
        q2s += __shfl_xor_sync(0xffffffffu, q2s, 1);
        m *= (1.0f / HIDn);
        float var = q2s * (1.0f / HIDn) - m * m;
        rs = rsqrtf(var + 1e-5f);
    }
    if (IB) __syncthreads();
    if (tid < 96) {
        #pragma unroll
        for (int i = 0; i < 9; i++) {
            int k = half * 18 + 2 * i;
            float v0 = (vloc[2 * i]     - m) * rs * __ldg(g + k)     + __ldg(bb + k);
            float v1 = (vloc[2 * i + 1] - m) * rs * __ldg(g + k + 1) + __ldg(bb + k + 1);
            h[k * Rn + r] = v0;
            h[(k + 1) * Rn + r] = v1;
            uint32_t hi, lo;
            bfpair(v0, v1, hi, lo);
            int p = half * 9 + i;
            int byte = (r * 96 + p * 4) ^ swzm<48>(r);
            SU[byte >> 2] = hi; SU[1152 + (byte >> 2)] = lo;
        }
    }
    for (int u = tid; u < 288; u += NT) {
        int rr2 = u % 48, p = 18 + u / 48;
        int byte = (rr2 * 96 + p * 4) ^ swzm<48>(rr2);
        SU[byte >> 2] = 0; SU[1152 + (byte >> 2)] = 0;
    }
}

// ---------------- K6: mega-kernel ---------------------------------------------
__global__ __launch_bounds__(NT, 5)
void k_mega(const float* __restrict__ W0,  const float* __restrict__ W1,
            const float* __restrict__ cb,  const float* __restrict__ tinb,
            const float* __restrict__ bq,  const float* __restrict__ bk,
            const float* __restrict__ bv,  const float* __restrict__ bo,
            const float* __restrict__ g1,  const float* __restrict__ b1,
            const float* __restrict__ fb1, const float* __restrict__ fb2,
            const float* __restrict__ g2,  const float* __restrict__ b2,
            const float* __restrict__ fcW, const float* __restrict__ fcb,
            float* __restrict__ out) {
    __shared__ __align__(16) float sh_h[HIDn * Rn];     // 1728
    __shared__ __align__(16) float sh_U[FFNn * Rn];     // 6912 (27648 B)
    __shared__ __align__(16) float sh_S[2304];          // 9216 B

    float* h = sh_h;
    float* U = sh_U;
    float* S = sh_S;
    float* x   = U;
    float* tx  = U + 672;
    float* cat = U + 1344;

    const int tid = threadIdx.x;
    const int warp = tid >> 5, lane = tid & 31;
    const int nbase = blockIdx.x * SEQ;

    // ---- stage self tiles ----
    for (int idx = tid; idx < SEQ * Tn * INF; idx += NT) {
        int s2 = idx / 336, u = idx % 336;
        int t = u / INF, f = u % INF;
        int n2 = nbase + s2;
        x  [f * Rn + s2 * Tn + t] = d_xn [n2 * 336 + u];
        cat[f * Rn + s2 * Tn + t] = d_xn2[n2 * 336 + u];
    }

    // ---- ChebConv gather ----
    {
        int s2 = tid >> 6, l = tid & 63;
        int n2 = nbase + s2;
        int b = n2 >> 9, c = n2 & (Cn - 1);
        float acc[6];
        #pragma unroll
        for (int i = 0; i < 6; i++) acc[i] = 0.0f;
        int start = d_off[c], end = d_off[c + 1];
        for (int e = start; e < end; e++) {
            int   rr = __ldg(d_brow + e);
            float w  = __ldg(d_bw + e);
            const float* nb = d_xn + (b * Cn + rr) * 336;
            #pragma unroll
            for (int i = 0; i < 6; i++) {
                int u = l + i * 64;
                if (u < 336) acc[i] = fmaf(w, nb[u], acc[i]);
            }
        }
        #pragma unroll
        for (int i = 0; i < 6; i++) {
            int u = l + i * 64;
            if (u < 336) {
                int t = u / INF, f = u % INF;
                tx[f * Rn + s2 * Tn + t] = acc[i];
            }
        }
    }
    __syncthreads();

    // ---- gate ----
    for (int idx = tid; idx < Rn * INF; idx += NT) {
        int r = idx % Rn, j = idx / Rn;
        float sacc = __ldg(cb + j);
        #pragma unroll
        for (int f = 0; f < INF; f++) {
            sacc = fmaf(x [f * Rn + r], __ldg(W0 + f * INF + j), sacc);
            sacc = fmaf(tx[f * Rn + r], __ldg(W1 + f * INF + j), sacc);
        }
        cat[(INF + j) * Rn + r] = __fdividef(1.0f, 1.0f + __expf(-sacc));
    }
    __syncthreads();

    // ---- tin (tensor): staged input in dead U space; epilogue emits h+PE+staged S ----
    stageA<32, 28>(cat, U + 4608, tid);
    __syncthreads();
    tmmC_tin(U + 4608, d_wbh, d_wbl, tinb, h, S, warp, lane);
    {
        uint32_t* SU = reinterpret_cast<uint32_t*>(S);
        for (int u = tid; u < 288; u += NT) {
            int r = u % 48, p = 18 + u / 48;
            int byte = (r * 96 + p * 4) ^ swzm<48>(r);
            SU[byte >> 2] = 0; SU[1152 + (byte >> 2)] = 0;
        }
    }
    __syncthreads();

    const float scale = 0.23570226039551584f;
    #pragma unroll 1
    for (int l = 0; l < 2; l++) {
        const uint32_t* wqh = d_wbh + OFF_QKVO + (l * 4 + 0) * 960;
        const uint32_t* wkh = d_wbh + OFF_QKVO + (l * 4 + 1) * 960;
        const uint32_t* wvh = d_wbh + OFF_QKVO + (l * 4 + 2) * 960;
        const uint32_t* woh = d_wbh + OFF_QKVO + (l * 4 + 3) * 960;
        const uint32_t* wql = d_wbl + OFF_QKVO + (l * 4 + 0) * 960;
        const uint32_t* wkl = d_wbl + OFF_QKVO + (l * 4 + 1) * 960;
        const uint32_t* wvl = d_wbl + OFF_QKVO + (l * 4 + 2) * 960;
        const uint32_t* wol = d_wbl + OFF_QKVO + (l * 4 + 3) * 960;
        const uint32_t* f1h = d_wbh + OFF_F1 + l * 3456;
        const uint32_t* f1l = d_wbl + OFF_F1 + l * 3456;
        const uint32_t* f2h = d_wbh + OFF_F2 + l * 2880;
        const uint32_t* f2l = d_wbl + OFF_F2 + l * 2880;
        const float* bq_l = bq + l * HIDn;  const float* bk_l = bk + l * HIDn;
        const float* bv_l = bv + l * HIDn;  const float* bo_l = bo + l * HIDn;
        const float* g1_l = g1 + l * HIDn;  const float* b1_l = b1 + l * HIDn;
        const float* g2_l = g2 + l * HIDn;  const float* b2_l = b2 + l * HIDn;
        const float* fb1_l = fb1 + l * FFNn; const float* fb2_l = fb2 + l * HIDn;

        // ---- q,k,v fused + balanced ----
        tmmC3_bal(S, wqh, wql, bq_l, U,
                     wkh, wkl, bk_l, U + 1728,
                     wvh, wvl, bv_l, U + 3456, warp, lane);
        __syncthreads();

        // ---- scores: 96 balanced tiles of 4i x 6j ----
        for (int tile = tid; tile < 96; tile += NT) {
            int bs = tile / 24, rem = tile % 24;
            int ig = rem % 6, jg = rem / 6;          // jg 0..3
            int s2 = bs >> 1, hh = bs & 1;
            const float* qb = U        + hh * HDn * Rn + s2 * Tn + ig * 4;
            const float* kb = U + 1728 + hh * HDn * Rn + s2 * Tn + jg * 6;
            uint64_t acc[12];
            #pragma unroll
            for (int i = 0; i < 12; i++) acc[i] = 0ull;
            #pragma unroll 2
            for (int d = 0; d < HDn; d++) {
                ulonglong2 qv = *(const ulonglong2*)(qb + d * Rn);
                float2 k01 = *(const float2*)(kb + d * Rn);
                float2 k23 = *(const float2*)(kb + d * Rn + 2);
                float2 k45 = *(const float2*)(kb + d * Rn + 4);
                uint64_t kk0 = pack2(k01.x), kk1 = pack2(k01.y);
                uint64_t kk2 = pack2(k23.x), kk3 = pack2(k23.y);
                uint64_t kk4 = pack2(k45.x), kk5 = pack2(k45.y);
                fma2(acc[0],  qv.x, kk0); fma2(acc[1],  qv.y, kk0);
                fma2(acc[2],  qv.x, kk1); fma2(acc[3],  qv.y, kk1);
                fma2(acc[4],  qv.x, kk2); fma2(acc[5],  qv.y, kk2);
                fma2(acc[6],  qv.x, kk3); fma2(acc[7],  qv.y, kk3);
                fma2(acc[8],  qv.x, kk4); fma2(acc[9],  qv.y, kk4);
                fma2(acc[10], qv.x, kk5); fma2(acc[11], qv.y, kk5);
            }
            int rowbase = s2 * 48 + hh * 24 + ig * 4;
            #pragma unroll
            for (int jj = 0; jj < 6; jj++) {
                float2 lo = unpack2(acc[2 * jj]);
                float2 hi = unpack2(acc[2 * jj + 1]);
                *(float4*)(S + (jg * 6 + jj) * 96 + rowbase) =
                    make_float4(lo.x * scale, lo.y * scale, hi.x * scale, hi.y * scale);
            }
        }
        __syncthreads();

        // softmax
        if (tid < 96) {
            float m = S[tid];
            #pragma unroll
            for (int j = 1; j < Tn; j++) m = fmaxf(m, S[j * 96 + tid]);
            float sum = 0.0f;
            #pragma unroll
            for (int j = 0; j < Tn; j++) {
                float e = __expf(S[j * 96 + tid] - m);
                S[j * 96 + tid] = e;
                sum += e;
            }
            float inv = __fdividef(1.0f, sum);
            #pragma unroll
            for (int j = 0; j < Tn; j++) S[j * 96 + tid] *= inv;
        }
        __syncthreads();

        // ---- attn out: staged bf16 [48][48] into U[0..2304) (q/k space, dead) ----
        {
            uint32_t* UU = reinterpret_cast<uint32_t*>(U);
            for (int tile = tid; tile < 216; tile += NT) {
                int s2 = tile / 108, rem = tile % 108;
                int og = rem / 6, tg = rem % 6;
                int o0 = og * 2, hh = o0 / HDn;
                const float* ab = S + s2 * 48 + hh * 24 + tg * 4;
                const float* vb = U + 3456 + o0 * Rn + s2 * Tn;
                uint64_t acc[4];
                #pragma unroll
                for (int i = 0; i < 4; i++) acc[i] = 0ull;
                #pragma unroll 4
                for (int j = 0; j < Tn; j++) {
                    ulonglong2 avv = *(const ulonglong2*)(ab + j * 96);
                    uint64_t p0 = pack2(vb[j]);
                    uint64_t p1 = pack2(vb[Rn + j]);
                    fma2(acc[0], avv.x, p0); fma2(acc[1], avv.y, p0);
                    fma2(acc[2], avv.x, p1); fma2(acc[3], avv.y, p1);
                }
                float2 a0 = unpack2(acc[0]), a1 = unpack2(acc[1]);
                float2 a2 = unpack2(acc[2]), a3 = unpack2(acc[3]);
                float v0s[4] = {a0.x, a0.y, a1.x, a1.y};
                float v1s[4] = {a2.x, a2.y, a3.x, a3.y};
                #pragma unroll
                for (int rr = 0; rr < 4; rr++) {
                    int m = s2 * Tn + tg * 4 + rr;
                    uint32_t hi, lo;
                    bfpair(v0s[rr], v1s[rr], hi, lo);
                    int byte = (m * 96 + og * 4) ^ swzm<48>(m);
                    UU[byte >> 2] = hi; UU[1152 + (byte >> 2)] = lo;
                }
            }
            for (int u = tid; u < 288; u += NT) {
                int r = u % 48, p = 18 + u / 48;
                int byte = (r * 96 + p * 4) ^ swzm<48>(r);
                UU[byte >> 2] = 0; UU[1152 + (byte >> 2)] = 0;
            }
        }
        __syncthreads();

        // ---- Wo (tensor, balanced): staged U -> fp32 U+5184 ----
        tmmC_bal<48, false>(U, woh, wol, bo_l, U + 5184, warp, lane);
        __syncthreads();

        // ---- LN1 -> h fp32 + staged S (no alias; no internal barrier) ----
        layernorm2s<false>(h, U + 5184, g1_l, b1_l, S, tid);
        __syncthreads();

        // ---- ffn1: staged S -> staged bf16 U (relu) ----
        tmmB(S, f1h, f1l, fb1_l, U, warp, lane);
        __syncthreads();

        // ---- ffn2 (balanced): staged U (KP=144) -> fp32 S ----
        tmmC_bal<144, false>(U, f2h, f2l, fb2_l, S, warp, lane);
        __syncthreads();

        // ---- LN2 -> h fp32 + staged S (res aliases Sst; internal barrier) ----
        layernorm2s<true>(h, S, g2_l, b2_l, S, tid);
        __syncthreads();
    }

    // ---- fc + store ----
    if (tid < Rn) {
        int r = tid;
        int s2 = r / Tn, t = r % Tn;
        int n2 = nbase + s2;
        int b = n2 >> 9, c = n2 & (Cn - 1);
        float acc = __ldg(fcb);
        #pragma unroll
        for (int k = 0; k < HIDn; k++) acc = fmaf(h[k * Rn + r], __ldg(fcW + k), acc);
        out[(b * Tn + t) * Cn + c] = acc;
    }
}

// ---------------- launch ------------------------------------------------------
extern "C" void kernel_launch(void* const* d_in, const int* in_sizes, int n_in,
                              void* d_out, int out_size) {
    const float *pm, *ft, *W0, *W1, *cb, *tinW, *tinb, *Wq, *bq, *Wk, *bk,
                *Wv, *bv, *Wo, *bo, *g1, *b1, *fW1, *fb1, *fW2, *fb2,
                *g2, *b2, *fcW, *fcb;
    const int* ei;

    if (in_sizes[2] == 2 * EG) {
        pm  = (const float*)d_in[0];  ft  = (const float*)d_in[1];
        ei  = (const int*)  d_in[2];
        W0  = (const float*)d_in[3];  W1  = (const float*)d_in[4];
        cb  = (const float*)d_in[5];
        tinW= (const float*)d_in[6];  tinb= (const float*)d_in[7];
        Wq  = (const float*)d_in[8];  bq  = (const float*)d_in[9];
        Wk  = (const float*)d_in[10]; bk  = (const float*)d_in[11];
        Wv  = (const float*)d_in[12]; bv  = (const float*)d_in[13];
        Wo  = (const float*)d_in[14]; bo  = (const float*)d_in[15];
        g1  = (const float*)d_in[16]; b1  = (const float*)d_in[17];
        fW1 = (const float*)d_in[18]; fb1 = (const float*)d_in[19];
        fW2 = (const float*)d_in[20]; fb2 = (const float*)d_in[21];
        g2  = (const float*)d_in[22]; b2  = (const float*)d_in[23];
        fcW = (const float*)d_in[24]; fcb = (const float*)d_in[25];
    } else {
        pm  = (const float*)d_in[0];  ft  = (const float*)d_in[1];
        W0  = (const float*)d_in[2];  W1  = (const float*)d_in[3];
        cb  = (const float*)d_in[4];
        tinW= (const float*)d_in[5];  tinb= (const float*)d_in[6];
        Wq  = (const float*)d_in[7];  bq  = (const float*)d_in[8];
        Wk  = (const float*)d_in[9];  bk  = (const float*)d_in[10];
        Wv  = (const float*)d_in[11]; bv  = (const float*)d_in[12];
        Wo  = (const float*)d_in[13]; bo  = (const float*)d_in[14];
        g1  = (const float*)d_in[15]; b1  = (const float*)d_in[16];
        fW1 = (const float*)d_in[17]; fb1 = (const float*)d_in[18];
        fW2 = (const float*)d_in[19]; fb2 = (const float*)d_in[20];
        g2  = (const float*)d_in[21]; b2  = (const float*)d_in[22];
        fcW = (const float*)d_in[23]; fcb = (const float*)d_in[24];
        ei  = (const int*)  d_in[25];
    }

    k_count<<<Cn, 32>>>(ei);
    k_scan <<<1, Cn>>>();
    k_fill <<<Cn, 32>>>(ei);
    {
        int total = Nn * Tn * INF;
        k_pack<<<(total + 255) / 256, 256>>>(pm, ft);
    }
    k_wprep<<<(WB_TOT + 255) / 256, 256>>>(tinW, Wq, Wk, Wv, Wo, fW1, fW2);
    k_mega<<<Nn / SEQ, NT>>>(W0, W1, cb, tinb,
                             bq, bk, bv, bo, g1, b1, fb1, fb2, g2, b2,
                             fcW, fcb, (float*)d_out);
}